// round 1
// baseline (speedup 1.0000x reference)
#include <cuda_runtime.h>
#include <math.h>

// Problem constants
#define CB   4
#define CL   512
#define CD   1024
#define CND  512
#define CED  64
#define CH   16
#define CMLP 2048
#define CDH  64
#define NTOK (CB*CL)        // 2048
#define MODW (6*CD)         // 6144
#define EPSF 1e-5f

// ---------------- scratch (device globals; no allocations allowed) ----------------
__device__ float g_sln[NTOK*CND];                  // LN(s)
__device__ float g_t1[NTOK*CND];                   // silu(lin1)
__device__ float g_mod[NTOK*MODW];                 // 6D modulation
__device__ float g_scores[(size_t)CB*CH*CL*CL];    // bias then scores then attn (in-place)
__device__ float g_x[NTOK*CD];                     // modulated LN activations
__device__ float g_qkv[NTOK*3*CD];
__device__ float g_o[NTOK*CD];
__device__ float g_h2[NTOK*CD];
__device__ float g_t2[NTOK*CMLP];

// ---------------- utils ----------------
__device__ __forceinline__ float warp_sum(float v) {
#pragma unroll
    for (int o = 16; o > 0; o >>= 1) v += __shfl_xor_sync(0xffffffffu, v, o);
    return v;
}
__device__ __forceinline__ float warp_max(float v) {
#pragma unroll
    for (int o = 16; o > 0; o >>= 1) v = fmaxf(v, __shfl_xor_sync(0xffffffffu, v, o));
    return v;
}

// ---------------- LN(s)*w+b for s: width 512, 128 threads ----------------
__global__ void __launch_bounds__(128) ln_affine512(
    const float* __restrict__ x, const float* __restrict__ w,
    const float* __restrict__ b, float* __restrict__ out)
{
    int row = blockIdx.x;
    const float4* xr = (const float4*)(x + (size_t)row * CND);
    float4 v = xr[threadIdx.x];
    float s  = v.x + v.y + v.z + v.w;
    float ss = v.x*v.x + v.y*v.y + v.z*v.z + v.w*v.w;
    s = warp_sum(s); ss = warp_sum(ss);
    __shared__ float sh[8];
    int wid = threadIdx.x >> 5, lid = threadIdx.x & 31;
    if (lid == 0) { sh[wid] = s; sh[4 + wid] = ss; }
    __syncthreads();
    s  = sh[0] + sh[1] + sh[2] + sh[3];
    ss = sh[4] + sh[5] + sh[6] + sh[7];
    float mean = s * (1.0f / CND);
    float var  = ss * (1.0f / CND) - mean * mean;
    float rinv = rsqrtf(var + EPSF);
    int d = threadIdx.x * 4;
    float4 wv = *(const float4*)(w + d);
    float4 bv = *(const float4*)(b + d);
    float4 o;
    o.x = (v.x - mean) * rinv * wv.x + bv.x;
    o.y = (v.y - mean) * rinv * wv.y + bv.y;
    o.z = (v.z - mean) * rinv * wv.z + bv.z;
    o.w = (v.w - mean) * rinv * wv.w + bv.w;
    ((float4*)(out + (size_t)row * CND))[threadIdx.x] = o;
}

// ---------------- LN(h)*(1+scale)+shift: width 1024, 256 threads ----------------
__global__ void __launch_bounds__(256) ln_mod1024(
    const float* __restrict__ x, const float* __restrict__ mod,
    int scale_off, int shift_off, float* __restrict__ out)
{
    int row = blockIdx.x;
    float4 v = ((const float4*)(x + (size_t)row * CD))[threadIdx.x];
    float s  = v.x + v.y + v.z + v.w;
    float ss = v.x*v.x + v.y*v.y + v.z*v.z + v.w*v.w;
    s = warp_sum(s); ss = warp_sum(ss);
    __shared__ float sh[16];
    int wid = threadIdx.x >> 5, lid = threadIdx.x & 31;
    if (lid == 0) { sh[wid] = s; sh[8 + wid] = ss; }
    __syncthreads();
    s = 0.f; ss = 0.f;
#pragma unroll
    for (int i = 0; i < 8; i++) { s += sh[i]; ss += sh[8 + i]; }
    float mean = s * (1.0f / CD);
    float var  = ss * (1.0f / CD) - mean * mean;
    float rinv = rsqrtf(var + EPSF);
    int d = threadIdx.x * 4;
    const float* mrow = mod + (size_t)row * MODW;
    float4 sc = *(const float4*)(mrow + scale_off + d);
    float4 sf = *(const float4*)(mrow + shift_off + d);
    float4 o;
    o.x = ((v.x - mean) * rinv) * (1.0f + sc.x) + sf.x;
    o.y = ((v.y - mean) * rinv) * (1.0f + sc.y) + sf.y;
    o.z = ((v.z - mean) * rinv) * (1.0f + sc.z) + sf.z;
    o.w = ((v.w - mean) * rinv) * (1.0f + sc.w) + sf.w;
    ((float4*)(out + (size_t)row * CD))[threadIdx.x] = o;
}

// ---------------- generic NT GEMM: C[M,N] = A[M,K] @ W[N,K]^T (+epilogue) ----------------
// EPI 0: C = acc + bias[n]
// EPI 1: C = silu(acc + bias[n])
// EPI 2: C = res[row,n] + (acc + bias[n]) * gate[row*MODW + gate_off + n]
template<int EPI>
__global__ void __launch_bounds__(256) gemm_nt(
    const float* __restrict__ A, const float* __restrict__ W,
    const float* __restrict__ bias, float* __restrict__ C,
    int M, int N, int K,
    const float* __restrict__ res, const float* __restrict__ gate, int gate_off)
{
    __shared__ float As[16][132];
    __shared__ float Ws[16][132];
    int bm = blockIdx.y * 128;
    int bn = blockIdx.x * 128;
    int tid = threadIdx.x;
    int tx = tid & 15, ty = tid >> 4;
    float acc[8][8];
#pragma unroll
    for (int i = 0; i < 8; i++)
#pragma unroll
        for (int j = 0; j < 8; j++) acc[i][j] = 0.f;

    for (int k0 = 0; k0 < K; k0 += 16) {
#pragma unroll
        for (int r = 0; r < 2; r++) {
            int id = tid + r * 256;         // 0..511
            int row = id >> 2;              // 0..127
            int kv  = (id & 3) * 4;         // 0,4,8,12
            float4 a = *(const float4*)(A + (size_t)(bm + row) * K + k0 + kv);
            As[kv + 0][row] = a.x; As[kv + 1][row] = a.y;
            As[kv + 2][row] = a.z; As[kv + 3][row] = a.w;
            float4 w = *(const float4*)(W + (size_t)(bn + row) * K + k0 + kv);
            Ws[kv + 0][row] = w.x; Ws[kv + 1][row] = w.y;
            Ws[kv + 2][row] = w.z; Ws[kv + 3][row] = w.w;
        }
        __syncthreads();
#pragma unroll
        for (int kk = 0; kk < 16; kk++) {
            float a[8], b[8];
            *(float4*)(a)     = *(const float4*)&As[kk][ty * 8];
            *(float4*)(a + 4) = *(const float4*)&As[kk][ty * 8 + 4];
            *(float4*)(b)     = *(const float4*)&Ws[kk][tx * 8];
            *(float4*)(b + 4) = *(const float4*)&Ws[kk][tx * 8 + 4];
#pragma unroll
            for (int i = 0; i < 8; i++)
#pragma unroll
                for (int j = 0; j < 8; j++)
                    acc[i][j] = fmaf(a[i], b[j], acc[i][j]);
        }
        __syncthreads();
    }

#pragma unroll
    for (int i = 0; i < 8; i++) {
        int row = bm + ty * 8 + i;
        float* cr = C + (size_t)row * N;
        const float* rr = (EPI == 2) ? res + (size_t)row * N : nullptr;
        const float* gr = (EPI == 2) ? gate + (size_t)row * MODW + gate_off : nullptr;
#pragma unroll
        for (int j = 0; j < 8; j++) {
            int col = bn + tx * 8 + j;
            float v = acc[i][j] + bias[col];
            if (EPI == 1) v = v / (1.0f + expf(-v));
            if (EPI == 2) v = rr[col] + v * gr[col];
            cr[col] = v;
        }
    }
}

// ---------------- edge bias: LN(p)*w+b einsum edge_w -> bias[B,H,L,L] ----------------
__global__ void __launch_bounds__(128) edge_bias_k(
    const float* __restrict__ p, const float* __restrict__ lnw, const float* __restrict__ lnb,
    const float* __restrict__ ew, const float* __restrict__ eb, float* __restrict__ bias)
{
    __shared__ float ewT[64][16];     // [k][h], rows 64B aligned
    __shared__ float lnws[64], lnbs[64], ebs[16];
    int tid = threadIdx.x;
    for (int i = tid; i < 1024; i += 128) {
        int h = i >> 6, k = i & 63;
        ewT[k][h] = ew[i];
    }
    if (tid < 64) { lnws[tid] = lnw[tid]; lnbs[tid] = lnb[tid]; }
    if (tid < 16) ebs[tid] = eb[tid];
    __syncthreads();

    size_t idx = (size_t)blockIdx.x * 128 + tid;   // 0..B*L*L-1
    const float4* pr = (const float4*)(p + idx * 64);
    float4 v[16];
    float s = 0.f, ss = 0.f;
#pragma unroll
    for (int q = 0; q < 16; q++) {
        v[q] = pr[q];
        s  += v[q].x + v[q].y + v[q].z + v[q].w;
        ss += v[q].x*v[q].x + v[q].y*v[q].y + v[q].z*v[q].z + v[q].w*v[q].w;
    }
    float mean = s * (1.0f / 64.0f);
    float var  = ss * (1.0f / 64.0f) - mean * mean;
    float rinv = rsqrtf(var + EPSF);

    float acc[16];
#pragma unroll
    for (int h = 0; h < 16; h++) acc[h] = 0.f;

#pragma unroll
    for (int q = 0; q < 16; q++) {
        float4 lw = *(const float4*)(lnws + q * 4);
        float4 lb = *(const float4*)(lnbs + q * 4);
        float pv[4] = { v[q].x, v[q].y, v[q].z, v[q].w };
        float wv[4] = { lw.x, lw.y, lw.z, lw.w };
        float bv[4] = { lb.x, lb.y, lb.z, lb.w };
#pragma unroll
        for (int u = 0; u < 4; u++) {
            int k = q * 4 + u;
            float pb = (pv[u] - mean) * rinv * wv[u] + bv[u];
            const float4* e4 = (const float4*)ewT[k];
#pragma unroll
            for (int g = 0; g < 4; g++) {
                float4 e = e4[g];
                acc[g*4+0] = fmaf(pb, e.x, acc[g*4+0]);
                acc[g*4+1] = fmaf(pb, e.y, acc[g*4+1]);
                acc[g*4+2] = fmaf(pb, e.z, acc[g*4+2]);
                acc[g*4+3] = fmaf(pb, e.w, acc[g*4+3]);
            }
        }
    }

    int b  = (int)(idx >> 18);
    int ij = (int)(idx & 262143);
    int i  = ij >> 9, j = ij & 511;
    float* bb = bias + (((size_t)b * 16) * 512 + i) * 512 + j;
#pragma unroll
    for (int h = 0; h < 16; h++)
        bb[(size_t)h * 512 * 512] = acc[h] + ebs[h];
}

// ---------------- scores: q.k/8 + bias (in-place on bias buffer) ----------------
__global__ void __launch_bounds__(256) score_kernel(
    const float* __restrict__ qkv, float* __restrict__ sc)
{
    __shared__ float Qs[64][68];   // [d][i]
    __shared__ float Ks[64][68];   // [d][j]
    int bh = blockIdx.z; int b = bh >> 4, h = bh & 15;
    int i0 = blockIdx.y * 64, j0 = blockIdx.x * 64;
    int tid = threadIdx.x;
    const float* qb = qkv + (size_t)(b * CL) * (3 * CD) + h * CDH;
#pragma unroll
    for (int r = 0; r < 4; r++) {
        int id = tid + r * 256;
        int row = id >> 4;          // 0..63
        int dv  = (id & 15) * 4;    // 0..60
        float4 q4 = *(const float4*)(qb + (size_t)(i0 + row) * (3 * CD) + dv);
        Qs[dv + 0][row] = q4.x; Qs[dv + 1][row] = q4.y;
        Qs[dv + 2][row] = q4.z; Qs[dv + 3][row] = q4.w;
        float4 k4 = *(const float4*)(qb + CD + (size_t)(j0 + row) * (3 * CD) + dv);
        Ks[dv + 0][row] = k4.x; Ks[dv + 1][row] = k4.y;
        Ks[dv + 2][row] = k4.z; Ks[dv + 3][row] = k4.w;
    }
    __syncthreads();
    int tx = tid & 15, ty = tid >> 4;
    float acc[4][4];
#pragma unroll
    for (int i = 0; i < 4; i++)
#pragma unroll
        for (int j = 0; j < 4; j++) acc[i][j] = 0.f;
#pragma unroll
    for (int kk = 0; kk < 64; kk++) {
        float4 a  = *(const float4*)&Qs[kk][ty * 4];
        float4 bb = *(const float4*)&Ks[kk][tx * 4];
        float av[4] = { a.x, a.y, a.z, a.w };
        float bv[4] = { bb.x, bb.y, bb.z, bb.w };
#pragma unroll
        for (int i = 0; i < 4; i++)
#pragma unroll
            for (int j = 0; j < 4; j++)
                acc[i][j] = fmaf(av[i], bv[j], acc[i][j]);
    }
    const float inv8 = 0.125f;
#pragma unroll
    for (int ii = 0; ii < 4; ii++) {
        float* sp = sc + ((size_t)bh * CL + i0 + ty * 4 + ii) * CL + j0 + tx * 4;
        float4 bv = *(float4*)sp;
        bv.x = fmaf(acc[ii][0], inv8, bv.x);
        bv.y = fmaf(acc[ii][1], inv8, bv.y);
        bv.z = fmaf(acc[ii][2], inv8, bv.z);
        bv.w = fmaf(acc[ii][3], inv8, bv.w);
        *(float4*)sp = bv;
    }
}

// ---------------- softmax over rows of 512, in-place ----------------
__global__ void __launch_bounds__(128) softmax512(float* __restrict__ s)
{
    size_t row = blockIdx.x;
    float4* r = (float4*)(s + row * 512);
    float4 v = r[threadIdx.x];
    float m = fmaxf(fmaxf(v.x, v.y), fmaxf(v.z, v.w));
    m = warp_max(m);
    __shared__ float sh[8];
    int wid = threadIdx.x >> 5, lid = threadIdx.x & 31;
    if (lid == 0) sh[wid] = m;
    __syncthreads();
    m = fmaxf(fmaxf(sh[0], sh[1]), fmaxf(sh[2], sh[3]));
    v.x = expf(v.x - m); v.y = expf(v.y - m);
    v.z = expf(v.z - m); v.w = expf(v.w - m);
    float su = v.x + v.y + v.z + v.w;
    su = warp_sum(su);
    if (lid == 0) sh[4 + wid] = su;
    __syncthreads();
    su = sh[4] + sh[5] + sh[6] + sh[7];
    float inv = 1.0f / su;
    v.x *= inv; v.y *= inv; v.z *= inv; v.w *= inv;
    r[threadIdx.x] = v;
}

// ---------------- attn @ V -> o[B,L,D] ----------------
__global__ void __launch_bounds__(256) attn_v_kernel(
    const float* __restrict__ attn, const float* __restrict__ qkv, float* __restrict__ o)
{
    __shared__ float Ats[16][68];  // [j][i]
    __shared__ float Vs[16][68];   // [j][d]
    int bh = blockIdx.y; int b = bh >> 4, h = bh & 15;
    int i0 = blockIdx.x * 64;
    int tid = threadIdx.x;
    int tx = tid & 15, ty = tid >> 4;
    float acc[4][4];
#pragma unroll
    for (int i = 0; i < 4; i++)
#pragma unroll
        for (int j = 0; j < 4; j++) acc[i][j] = 0.f;

    const float* abase = attn + ((size_t)bh * CL + i0) * CL;
    const float* vbase = qkv + (size_t)(b * CL) * (3 * CD) + 2 * CD + h * CDH;

    for (int j0 = 0; j0 < CL; j0 += 16) {
        {
            int row = tid >> 2;            // 0..63 (i)
            int jv  = (tid & 3) * 4;       // 0,4,8,12
            float4 a = *(const float4*)(abase + (size_t)row * CL + j0 + jv);
            Ats[jv + 0][row] = a.x; Ats[jv + 1][row] = a.y;
            Ats[jv + 2][row] = a.z; Ats[jv + 3][row] = a.w;
            int vr = tid >> 4;             // 0..15 (j)
            int dv = (tid & 15) * 4;       // 0..60
            float4 vv = *(const float4*)(vbase + (size_t)(j0 + vr) * (3 * CD) + dv);
            *(float4*)&Vs[vr][dv] = vv;
        }
        __syncthreads();
#pragma unroll
        for (int kk = 0; kk < 16; kk++) {
            float4 a  = *(const float4*)&Ats[kk][ty * 4];
            float4 bb = *(const float4*)&Vs[kk][tx * 4];
            float av[4] = { a.x, a.y, a.z, a.w };
            float bv[4] = { bb.x, bb.y, bb.z, bb.w };
#pragma unroll
            for (int i = 0; i < 4; i++)
#pragma unroll
                for (int j = 0; j < 4; j++)
                    acc[i][j] = fmaf(av[i], bv[j], acc[i][j]);
        }
        __syncthreads();
    }
#pragma unroll
    for (int ii = 0; ii < 4; ii++) {
        float* op = o + (size_t)(b * CL + i0 + ty * 4 + ii) * CD + h * CDH + tx * 4;
        float4 w;
        w.x = acc[ii][0]; w.y = acc[ii][1]; w.z = acc[ii][2]; w.w = acc[ii][3];
        *(float4*)op = w;
    }
}

// ---------------- launch ----------------
extern "C" void kernel_launch(void* const* d_in, const int* in_sizes, int n_in,
                              void* d_out, int out_size)
{
    const float* h_in  = (const float*)d_in[0];
    const float* s_in  = (const float*)d_in[1];
    const float* p_in  = (const float*)d_in[2];
    const float* aln_w = (const float*)d_in[3];
    const float* aln_b = (const float*)d_in[4];
    const float* aw1   = (const float*)d_in[5];
    const float* ab1   = (const float*)d_in[6];
    const float* aw2   = (const float*)d_in[7];
    const float* ab2   = (const float*)d_in[8];
    const float* eln_w = (const float*)d_in[9];
    const float* eln_b = (const float*)d_in[10];
    const float* ew    = (const float*)d_in[11];
    const float* eb    = (const float*)d_in[12];
    const float* in_w  = (const float*)d_in[13];
    const float* in_b  = (const float*)d_in[14];
    const float* out_w = (const float*)d_in[15];
    const float* out_b = (const float*)d_in[16];
    const float* mw1   = (const float*)d_in[17];
    const float* mb1   = (const float*)d_in[18];
    const float* mw2   = (const float*)d_in[19];
    const float* mb2   = (const float*)d_in[20];
    float* out = (float*)d_out;

    float *sln, *t1, *mod, *scores, *x, *qkv, *o, *h2, *t2;
    cudaGetSymbolAddress((void**)&sln,    g_sln);
    cudaGetSymbolAddress((void**)&t1,     g_t1);
    cudaGetSymbolAddress((void**)&mod,    g_mod);
    cudaGetSymbolAddress((void**)&scores, g_scores);
    cudaGetSymbolAddress((void**)&x,      g_x);
    cudaGetSymbolAddress((void**)&qkv,    g_qkv);
    cudaGetSymbolAddress((void**)&o,      g_o);
    cudaGetSymbolAddress((void**)&h2,     g_h2);
    cudaGetSymbolAddress((void**)&t2,     g_t2);

    // adaLN modulation chain
    ln_affine512<<<NTOK, 128>>>(s_in, aln_w, aln_b, sln);
    gemm_nt<1><<<dim3(CND / 128, NTOK / 128), 256>>>(sln, aw1, ab1, t1,
        NTOK, CND, CND, nullptr, nullptr, 0);
    gemm_nt<0><<<dim3(MODW / 128, NTOK / 128), 256>>>(t1, aw2, ab2, mod,
        NTOK, MODW, CND, nullptr, nullptr, 0);

    // edge bias (writes into scores buffer)
    edge_bias_k<<<(CB * CL * CL) / 128, 128>>>(p_in, eln_w, eln_b, ew, eb, scores);

    // attention branch
    ln_mod1024<<<NTOK, 256>>>(h_in, mod, /*scale*/CD, /*shift*/0, x);
    gemm_nt<0><<<dim3(3 * CD / 128, NTOK / 128), 256>>>(x, in_w, in_b, qkv,
        NTOK, 3 * CD, CD, nullptr, nullptr, 0);
    score_kernel<<<dim3(8, 8, CB * CH), 256>>>(qkv, scores);
    softmax512<<<CB * CH * CL, 128>>>(scores);
    attn_v_kernel<<<dim3(8, CB * CH), 256>>>(scores, qkv, o);
    gemm_nt<2><<<dim3(CD / 128, NTOK / 128), 256>>>(o, out_w, out_b, h2,
        NTOK, CD, CD, h_in, mod, 2 * CD);

    // gated MLP branch
    ln_mod1024<<<NTOK, 256>>>(h2, mod, /*scale*/4 * CD, /*shift*/3 * CD, x);
    gemm_nt<1><<<dim3(CMLP / 128, NTOK / 128), 256>>>(x, mw1, mb1, t2,
        NTOK, CMLP, CD, nullptr, nullptr, 0);
    gemm_nt<2><<<dim3(CD / 128, NTOK / 128), 256>>>(t2, mw2, mb2, out,
        NTOK, CD, CMLP, h2, mod, 5 * CD);
}

// round 2
// speedup vs baseline: 1.9086x; 1.9086x over previous
#include <cuda_runtime.h>
#include <math.h>
#include <stdint.h>

// Problem constants
#define CB   4
#define CL   512
#define CD   1024
#define CND  512
#define CED  64
#define CH   16
#define CMLP 2048
#define CDH  64
#define NTOK (CB*CL)        // 2048
#define MODW (6*CD)         // 6144
#define EPSF 1e-5f

// ---------------- scratch (device globals; no allocations allowed) ----------------
__device__ float g_sln[NTOK*CND];                  // LN(s)
__device__ float g_t1[NTOK*CND];                   // silu(lin1)
__device__ float g_mod[NTOK*MODW];                 // 6D modulation
__device__ float g_scores[(size_t)CB*CH*CL*CL];    // bias then scores then attn (in-place)
__device__ float g_x[NTOK*CD];                     // modulated LN activations
__device__ float g_qkv[NTOK*3*CD];
__device__ float g_o[NTOK*CD];
__device__ float g_h2[NTOK*CD];
__device__ float g_t2[NTOK*CMLP];

// ---------------- utils ----------------
__device__ __forceinline__ float warp_sum(float v) {
#pragma unroll
    for (int o = 16; o > 0; o >>= 1) v += __shfl_xor_sync(0xffffffffu, v, o);
    return v;
}
__device__ __forceinline__ float warp_max(float v) {
#pragma unroll
    for (int o = 16; o > 0; o >>= 1) v = fmaxf(v, __shfl_xor_sync(0xffffffffu, v, o));
    return v;
}
__device__ __forceinline__ uint32_t f2tf32(float f) {
    uint32_t r;
    asm("cvt.rna.tf32.f32 %0, %1;" : "=r"(r) : "f"(f));
    return r;
}
__device__ __forceinline__ void mma_tf32(float c[4], const uint32_t a[4], const uint32_t b[2]) {
    asm volatile(
        "mma.sync.aligned.m16n8k8.row.col.f32.tf32.tf32.f32 "
        "{%0,%1,%2,%3}, {%4,%5,%6,%7}, {%8,%9}, {%0,%1,%2,%3};"
        : "+f"(c[0]), "+f"(c[1]), "+f"(c[2]), "+f"(c[3])
        : "r"(a[0]), "r"(a[1]), "r"(a[2]), "r"(a[3]), "r"(b[0]), "r"(b[1]));
}

// ---------------- LN(s)*w+b for s: width 512, 128 threads ----------------
__global__ void __launch_bounds__(128) ln_affine512(
    const float* __restrict__ x, const float* __restrict__ w,
    const float* __restrict__ b, float* __restrict__ out)
{
    int row = blockIdx.x;
    const float4* xr = (const float4*)(x + (size_t)row * CND);
    float4 v = xr[threadIdx.x];
    float s  = v.x + v.y + v.z + v.w;
    float ss = v.x*v.x + v.y*v.y + v.z*v.z + v.w*v.w;
    s = warp_sum(s); ss = warp_sum(ss);
    __shared__ float sh[8];
    int wid = threadIdx.x >> 5, lid = threadIdx.x & 31;
    if (lid == 0) { sh[wid] = s; sh[4 + wid] = ss; }
    __syncthreads();
    s  = sh[0] + sh[1] + sh[2] + sh[3];
    ss = sh[4] + sh[5] + sh[6] + sh[7];
    float mean = s * (1.0f / CND);
    float var  = ss * (1.0f / CND) - mean * mean;
    float rinv = rsqrtf(var + EPSF);
    int d = threadIdx.x * 4;
    float4 wv = *(const float4*)(w + d);
    float4 bv = *(const float4*)(b + d);
    float4 o;
    o.x = (v.x - mean) * rinv * wv.x + bv.x;
    o.y = (v.y - mean) * rinv * wv.y + bv.y;
    o.z = (v.z - mean) * rinv * wv.z + bv.z;
    o.w = (v.w - mean) * rinv * wv.w + bv.w;
    ((float4*)(out + (size_t)row * CND))[threadIdx.x] = o;
}

// ---------------- LN(h)*(1+scale)+shift: width 1024, 256 threads ----------------
__global__ void __launch_bounds__(256) ln_mod1024(
    const float* __restrict__ x, const float* __restrict__ mod,
    int scale_off, int shift_off, float* __restrict__ out)
{
    int row = blockIdx.x;
    float4 v = ((const float4*)(x + (size_t)row * CD))[threadIdx.x];
    float s  = v.x + v.y + v.z + v.w;
    float ss = v.x*v.x + v.y*v.y + v.z*v.z + v.w*v.w;
    s = warp_sum(s); ss = warp_sum(ss);
    __shared__ float sh[16];
    int wid = threadIdx.x >> 5, lid = threadIdx.x & 31;
    if (lid == 0) { sh[wid] = s; sh[8 + wid] = ss; }
    __syncthreads();
    s = 0.f; ss = 0.f;
#pragma unroll
    for (int i = 0; i < 8; i++) { s += sh[i]; ss += sh[8 + i]; }
    float mean = s * (1.0f / CD);
    float var  = ss * (1.0f / CD) - mean * mean;
    float rinv = rsqrtf(var + EPSF);
    int d = threadIdx.x * 4;
    const float* mrow = mod + (size_t)row * MODW;
    float4 sc = *(const float4*)(mrow + scale_off + d);
    float4 sf = *(const float4*)(mrow + shift_off + d);
    float4 o;
    o.x = ((v.x - mean) * rinv) * (1.0f + sc.x) + sf.x;
    o.y = ((v.y - mean) * rinv) * (1.0f + sc.y) + sf.y;
    o.z = ((v.z - mean) * rinv) * (1.0f + sc.z) + sf.z;
    o.w = ((v.w - mean) * rinv) * (1.0f + sc.w) + sf.w;
    ((float4*)(out + (size_t)row * CD))[threadIdx.x] = o;
}

// ---------------- tf32 tensor-core NT GEMM: C[M,N] = A[M,K] @ W[N,K]^T ----------------
// Block 128x128x32, 256 threads (8 warps as 2x4), warp tile 64x32 via m16n8k8.
// EPI 0: C = acc + bias[n]
// EPI 1: C = silu(acc + bias[n])
// EPI 2: C = res[row,n] + (acc + bias[n]) * gate[row*MODW + gate_off + n]
template<int EPI>
__global__ void __launch_bounds__(256) gemm_tf32(
    const float* __restrict__ A, const float* __restrict__ W,
    const float* __restrict__ bias, float* __restrict__ C,
    int M, int N, int K,
    const float* __restrict__ res, const float* __restrict__ gate, int gate_off)
{
    __shared__ uint32_t As[128][36];   // [m][k], pad 36 -> bank=(4m+k)%32 conflict-free
    __shared__ uint32_t Ws[128][36];   // [n][k]
    int bm = blockIdx.y * 128;
    int bn = blockIdx.x * 128;
    int tid  = threadIdx.x;
    int warp = tid >> 5, lane = tid & 31;
    int g = lane >> 2, t = lane & 3;
    int wm = (warp & 1) * 64;          // warp M offset
    int wn = (warp >> 1) * 32;         // warp N offset

    float acc[4][4][4];
#pragma unroll
    for (int i = 0; i < 4; i++)
#pragma unroll
        for (int j = 0; j < 4; j++)
#pragma unroll
            for (int q = 0; q < 4; q++) acc[i][j][q] = 0.f;

    for (int k0 = 0; k0 < K; k0 += 32) {
        // stage A and W tiles (converted to tf32)
#pragma unroll
        for (int r = 0; r < 4; r++) {
            int id  = tid + r * 256;        // 0..1023
            int row = id >> 3;              // 0..127
            int kv  = (id & 7) * 4;         // 0..28
            float4 a = *(const float4*)(A + (size_t)(bm + row) * K + k0 + kv);
            As[row][kv + 0] = f2tf32(a.x); As[row][kv + 1] = f2tf32(a.y);
            As[row][kv + 2] = f2tf32(a.z); As[row][kv + 3] = f2tf32(a.w);
            float4 w = *(const float4*)(W + (size_t)(bn + row) * K + k0 + kv);
            Ws[row][kv + 0] = f2tf32(w.x); Ws[row][kv + 1] = f2tf32(w.y);
            Ws[row][kv + 2] = f2tf32(w.z); Ws[row][kv + 3] = f2tf32(w.w);
        }
        __syncthreads();

#pragma unroll
        for (int ks = 0; ks < 4; ks++) {
            int kk = ks * 8;
            uint32_t af[4][4];
#pragma unroll
            for (int mt = 0; mt < 4; mt++) {
                int r0 = wm + mt * 16 + g;
                af[mt][0] = As[r0][kk + t];
                af[mt][1] = As[r0 + 8][kk + t];
                af[mt][2] = As[r0][kk + t + 4];
                af[mt][3] = As[r0 + 8][kk + t + 4];
            }
            uint32_t bf[4][2];
#pragma unroll
            for (int nt = 0; nt < 4; nt++) {
                int c0 = wn + nt * 8 + g;
                bf[nt][0] = Ws[c0][kk + t];
                bf[nt][1] = Ws[c0][kk + t + 4];
            }
#pragma unroll
            for (int mt = 0; mt < 4; mt++)
#pragma unroll
                for (int nt = 0; nt < 4; nt++)
                    mma_tf32(acc[mt][nt], af[mt], bf[nt]);
        }
        __syncthreads();
    }

    // epilogue: each thread owns (rows g, g+8) x (cols 2t, 2t+1) per 16x8 tile
#pragma unroll
    for (int mt = 0; mt < 4; mt++) {
#pragma unroll
        for (int half = 0; half < 2; half++) {
            int row = bm + wm + mt * 16 + g + half * 8;
            float* cr = C + (size_t)row * N;
            const float* rr = (EPI == 2) ? res + (size_t)row * N : nullptr;
            const float* gr = (EPI == 2) ? gate + (size_t)row * MODW + gate_off : nullptr;
#pragma unroll
            for (int nt = 0; nt < 4; nt++) {
                int col = bn + wn + nt * 8 + 2 * t;
                float v0 = acc[mt][nt][half * 2 + 0] + bias[col];
                float v1 = acc[mt][nt][half * 2 + 1] + bias[col + 1];
                if (EPI == 1) {
                    v0 = v0 / (1.0f + expf(-v0));
                    v1 = v1 / (1.0f + expf(-v1));
                }
                if (EPI == 2) {
                    v0 = rr[col]     + v0 * gr[col];
                    v1 = rr[col + 1] + v1 * gr[col + 1];
                }
                float2 o2; o2.x = v0; o2.y = v1;
                *(float2*)(cr + col) = o2;
            }
        }
    }
}

// ---------------- edge bias: LN(p)*w+b einsum edge_w -> bias[B,H,L,L] ----------------
__global__ void __launch_bounds__(128) edge_bias_k(
    const float* __restrict__ p, const float* __restrict__ lnw, const float* __restrict__ lnb,
    const float* __restrict__ ew, const float* __restrict__ eb, float* __restrict__ bias)
{
    __shared__ float ewT[64][16];     // [k][h]
    __shared__ float lnws[64], lnbs[64], ebs[16];
    int tid = threadIdx.x;
    for (int i = tid; i < 1024; i += 128) {
        int h = i >> 6, k = i & 63;
        ewT[k][h] = ew[i];
    }
    if (tid < 64) { lnws[tid] = lnw[tid]; lnbs[tid] = lnb[tid]; }
    if (tid < 16) ebs[tid] = eb[tid];
    __syncthreads();

    size_t idx = (size_t)blockIdx.x * 128 + tid;   // 0..B*L*L-1
    const float4* pr = (const float4*)(p + idx * 64);
    float4 v[16];
    float s = 0.f, ss = 0.f;
#pragma unroll
    for (int q = 0; q < 16; q++) {
        v[q] = pr[q];
        s  += v[q].x + v[q].y + v[q].z + v[q].w;
        ss += v[q].x*v[q].x + v[q].y*v[q].y + v[q].z*v[q].z + v[q].w*v[q].w;
    }
    float mean = s * (1.0f / 64.0f);
    float var  = ss * (1.0f / 64.0f) - mean * mean;
    float rinv = rsqrtf(var + EPSF);

    float acc[16];
#pragma unroll
    for (int h = 0; h < 16; h++) acc[h] = 0.f;

#pragma unroll
    for (int q = 0; q < 16; q++) {
        float4 lw = *(const float4*)(lnws + q * 4);
        float4 lb = *(const float4*)(lnbs + q * 4);
        float pv[4] = { v[q].x, v[q].y, v[q].z, v[q].w };
        float wv[4] = { lw.x, lw.y, lw.z, lw.w };
        float bv[4] = { lb.x, lb.y, lb.z, lb.w };
#pragma unroll
        for (int u = 0; u < 4; u++) {
            int k = q * 4 + u;
            float pb = (pv[u] - mean) * rinv * wv[u] + bv[u];
            const float4* e4 = (const float4*)ewT[k];
#pragma unroll
            for (int gi = 0; gi < 4; gi++) {
                float4 e = e4[gi];
                acc[gi*4+0] = fmaf(pb, e.x, acc[gi*4+0]);
                acc[gi*4+1] = fmaf(pb, e.y, acc[gi*4+1]);
                acc[gi*4+2] = fmaf(pb, e.z, acc[gi*4+2]);
                acc[gi*4+3] = fmaf(pb, e.w, acc[gi*4+3]);
            }
        }
    }

    int b  = (int)(idx >> 18);
    int ij = (int)(idx & 262143);
    int i  = ij >> 9, j = ij & 511;
    float* bb = bias + (((size_t)b * 16) * 512 + i) * 512 + j;
#pragma unroll
    for (int h = 0; h < 16; h++)
        bb[(size_t)h * 512 * 512] = acc[h] + ebs[h];
}

// ---------------- scores: q.k/8 + bias (in-place on bias buffer) ----------------
__global__ void __launch_bounds__(256) score_kernel(
    const float* __restrict__ qkv, float* __restrict__ sc)
{
    __shared__ float Qs[64][68];   // [d][i]
    __shared__ float Ks[64][68];   // [d][j]
    int bh = blockIdx.z; int b = bh >> 4, h = bh & 15;
    int i0 = blockIdx.y * 64, j0 = blockIdx.x * 64;
    int tid = threadIdx.x;
    const float* qb = qkv + (size_t)(b * CL) * (3 * CD) + h * CDH;
#pragma unroll
    for (int r = 0; r < 4; r++) {
        int id = tid + r * 256;
        int row = id >> 4;          // 0..63
        int dv  = (id & 15) * 4;    // 0..60
        float4 q4 = *(const float4*)(qb + (size_t)(i0 + row) * (3 * CD) + dv);
        Qs[dv + 0][row] = q4.x; Qs[dv + 1][row] = q4.y;
        Qs[dv + 2][row] = q4.z; Qs[dv + 3][row] = q4.w;
        float4 k4 = *(const float4*)(qb + CD + (size_t)(j0 + row) * (3 * CD) + dv);
        Ks[dv + 0][row] = k4.x; Ks[dv + 1][row] = k4.y;
        Ks[dv + 2][row] = k4.z; Ks[dv + 3][row] = k4.w;
    }
    __syncthreads();
    int tx = tid & 15, ty = tid >> 4;
    float acc[4][4];
#pragma unroll
    for (int i = 0; i < 4; i++)
#pragma unroll
        for (int j = 0; j < 4; j++) acc[i][j] = 0.f;
#pragma unroll
    for (int kk = 0; kk < 64; kk++) {
        float4 a  = *(const float4*)&Qs[kk][ty * 4];
        float4 bb = *(const float4*)&Ks[kk][tx * 4];
        float av[4] = { a.x, a.y, a.z, a.w };
        float bv[4] = { bb.x, bb.y, bb.z, bb.w };
#pragma unroll
        for (int i = 0; i < 4; i++)
#pragma unroll
            for (int j = 0; j < 4; j++)
                acc[i][j] = fmaf(av[i], bv[j], acc[i][j]);
    }
    const float inv8 = 0.125f;
#pragma unroll
    for (int ii = 0; ii < 4; ii++) {
        float* sp = sc + ((size_t)bh * CL + i0 + ty * 4 + ii) * CL + j0 + tx * 4;
        float4 bv = *(float4*)sp;
        bv.x = fmaf(acc[ii][0], inv8, bv.x);
        bv.y = fmaf(acc[ii][1], inv8, bv.y);
        bv.z = fmaf(acc[ii][2], inv8, bv.z);
        bv.w = fmaf(acc[ii][3], inv8, bv.w);
        *(float4*)sp = bv;
    }
}

// ---------------- softmax over rows of 512, in-place ----------------
__global__ void __launch_bounds__(128) softmax512(float* __restrict__ s)
{
    size_t row = blockIdx.x;
    float4* r = (float4*)(s + row * 512);
    float4 v = r[threadIdx.x];
    float m = fmaxf(fmaxf(v.x, v.y), fmaxf(v.z, v.w));
    m = warp_max(m);
    __shared__ float sh[8];
    int wid = threadIdx.x >> 5, lid = threadIdx.x & 31;
    if (lid == 0) sh[wid] = m;
    __syncthreads();
    m = fmaxf(fmaxf(sh[0], sh[1]), fmaxf(sh[2], sh[3]));
    v.x = expf(v.x - m); v.y = expf(v.y - m);
    v.z = expf(v.z - m); v.w = expf(v.w - m);
    float su = v.x + v.y + v.z + v.w;
    su = warp_sum(su);
    if (lid == 0) sh[4 + wid] = su;
    __syncthreads();
    su = sh[4] + sh[5] + sh[6] + sh[7];
    float inv = 1.0f / su;
    v.x *= inv; v.y *= inv; v.z *= inv; v.w *= inv;
    r[threadIdx.x] = v;
}

// ---------------- attn @ V -> o[B,L,D] ----------------
__global__ void __launch_bounds__(256) attn_v_kernel(
    const float* __restrict__ attn, const float* __restrict__ qkv, float* __restrict__ o)
{
    __shared__ float Ats[16][68];  // [j][i]
    __shared__ float Vs[16][68];   // [j][d]
    int bh = blockIdx.y; int b = bh >> 4, h = bh & 15;
    int i0 = blockIdx.x * 64;
    int tid = threadIdx.x;
    int tx = tid & 15, ty = tid >> 4;
    float acc[4][4];
#pragma unroll
    for (int i = 0; i < 4; i++)
#pragma unroll
        for (int j = 0; j < 4; j++) acc[i][j] = 0.f;

    const float* abase = attn + ((size_t)bh * CL + i0) * CL;
    const float* vbase = qkv + (size_t)(b * CL) * (3 * CD) + 2 * CD + h * CDH;

    for (int j0 = 0; j0 < CL; j0 += 16) {
        {
            int row = tid >> 2;            // 0..63 (i)
            int jv  = (tid & 3) * 4;       // 0,4,8,12
            float4 a = *(const float4*)(abase + (size_t)row * CL + j0 + jv);
            Ats[jv + 0][row] = a.x; Ats[jv + 1][row] = a.y;
            Ats[jv + 2][row] = a.z; Ats[jv + 3][row] = a.w;
            int vr = tid >> 4;             // 0..15 (j)
            int dv = (tid & 15) * 4;       // 0..60
            float4 vv = *(const float4*)(vbase + (size_t)(j0 + vr) * (3 * CD) + dv);
            *(float4*)&Vs[vr][dv] = vv;
        }
        __syncthreads();
#pragma unroll
        for (int kk = 0; kk < 16; kk++) {
            float4 a  = *(const float4*)&Ats[kk][ty * 4];
            float4 bb = *(const float4*)&Vs[kk][tx * 4];
            float av[4] = { a.x, a.y, a.z, a.w };
            float bv[4] = { bb.x, bb.y, bb.z, bb.w };
#pragma unroll
            for (int i = 0; i < 4; i++)
#pragma unroll
                for (int j = 0; j < 4; j++)
                    acc[i][j] = fmaf(av[i], bv[j], acc[i][j]);
        }
        __syncthreads();
    }
#pragma unroll
    for (int ii = 0; ii < 4; ii++) {
        float* op = o + (size_t)(b * CL + i0 + ty * 4 + ii) * CD + h * CDH + tx * 4;
        float4 w;
        w.x = acc[ii][0]; w.y = acc[ii][1]; w.z = acc[ii][2]; w.w = acc[ii][3];
        *(float4*)op = w;
    }
}

// ---------------- launch ----------------
extern "C" void kernel_launch(void* const* d_in, const int* in_sizes, int n_in,
                              void* d_out, int out_size)
{
    const float* h_in  = (const float*)d_in[0];
    const float* s_in  = (const float*)d_in[1];
    const float* p_in  = (const float*)d_in[2];
    const float* aln_w = (const float*)d_in[3];
    const float* aln_b = (const float*)d_in[4];
    const float* aw1   = (const float*)d_in[5];
    const float* ab1   = (const float*)d_in[6];
    const float* aw2   = (const float*)d_in[7];
    const float* ab2   = (const float*)d_in[8];
    const float* eln_w = (const float*)d_in[9];
    const float* eln_b = (const float*)d_in[10];
    const float* ew    = (const float*)d_in[11];
    const float* eb    = (const float*)d_in[12];
    const float* in_w  = (const float*)d_in[13];
    const float* in_b  = (const float*)d_in[14];
    const float* out_w = (const float*)d_in[15];
    const float* out_b = (const float*)d_in[16];
    const float* mw1   = (const float*)d_in[17];
    const float* mb1   = (const float*)d_in[18];
    const float* mw2   = (const float*)d_in[19];
    const float* mb2   = (const float*)d_in[20];
    float* out = (float*)d_out;

    float *sln, *t1, *mod, *scores, *x, *qkv, *o, *h2, *t2;
    cudaGetSymbolAddress((void**)&sln,    g_sln);
    cudaGetSymbolAddress((void**)&t1,     g_t1);
    cudaGetSymbolAddress((void**)&mod,    g_mod);
    cudaGetSymbolAddress((void**)&scores, g_scores);
    cudaGetSymbolAddress((void**)&x,      g_x);
    cudaGetSymbolAddress((void**)&qkv,    g_qkv);
    cudaGetSymbolAddress((void**)&o,      g_o);
    cudaGetSymbolAddress((void**)&h2,     g_h2);
    cudaGetSymbolAddress((void**)&t2,     g_t2);

    // adaLN modulation chain
    ln_affine512<<<NTOK, 128>>>(s_in, aln_w, aln_b, sln);
    gemm_tf32<1><<<dim3(CND / 128, NTOK / 128), 256>>>(sln, aw1, ab1, t1,
        NTOK, CND, CND, nullptr, nullptr, 0);
    gemm_tf32<0><<<dim3(MODW / 128, NTOK / 128), 256>>>(t1, aw2, ab2, mod,
        NTOK, MODW, CND, nullptr, nullptr, 0);

    // edge bias (writes into scores buffer)
    edge_bias_k<<<(CB * CL * CL) / 128, 128>>>(p_in, eln_w, eln_b, ew, eb, scores);

    // attention branch
    ln_mod1024<<<NTOK, 256>>>(h_in, mod, /*scale*/CD, /*shift*/0, x);
    gemm_tf32<0><<<dim3(3 * CD / 128, NTOK / 128), 256>>>(x, in_w, in_b, qkv,
        NTOK, 3 * CD, CD, nullptr, nullptr, 0);
    score_kernel<<<dim3(8, 8, CB * CH), 256>>>(qkv, scores);
    softmax512<<<CB * CH * CL, 128>>>(scores);
    attn_v_kernel<<<dim3(8, CB * CH), 256>>>(scores, qkv, o);
    gemm_tf32<2><<<dim3(CD / 128, NTOK / 128), 256>>>(o, out_w, out_b, h2,
        NTOK, CD, CD, h_in, mod, 2 * CD);

    // gated MLP branch
    ln_mod1024<<<NTOK, 256>>>(h2, mod, /*scale*/4 * CD, /*shift*/3 * CD, x);
    gemm_tf32<1><<<dim3(CMLP / 128, NTOK / 128), 256>>>(x, mw1, mb1, t2,
        NTOK, CMLP, CD, nullptr, nullptr, 0);
    gemm_tf32<2><<<dim3(CD / 128, NTOK / 128), 256>>>(t2, mw2, mb2, out,
        NTOK, CD, CMLP, h2, mod, 5 * CD);
}

// round 3
// speedup vs baseline: 2.5441x; 1.3329x over previous
#include <cuda_runtime.h>
#include <math.h>
#include <stdint.h>

// Problem constants
#define CB   4
#define CL   512
#define CD   1024
#define CND  512
#define CED  64
#define CH   16
#define CMLP 2048
#define CDH  64
#define NTOK (CB*CL)        // 2048
#define MODW (6*CD)         // 6144
#define EPSF 1e-5f

// ---------------- scratch (device globals; no allocations allowed) ----------------
__device__ float g_sln[NTOK*CND];
__device__ float g_t1[NTOK*CND];
__device__ float g_mod[NTOK*MODW];
__device__ float g_scores[(size_t)CB*CH*CL*CL];
__device__ float g_x[NTOK*CD];
__device__ float g_qkv[NTOK*3*CD];
__device__ float g_o[NTOK*CD];
__device__ float g_h2[NTOK*CD];
__device__ float g_t2[NTOK*CMLP];

// ---------------- utils ----------------
__device__ __forceinline__ float warp_sum(float v) {
#pragma unroll
    for (int o = 16; o > 0; o >>= 1) v += __shfl_xor_sync(0xffffffffu, v, o);
    return v;
}
__device__ __forceinline__ float warp_max(float v) {
#pragma unroll
    for (int o = 16; o > 0; o >>= 1) v = fmaxf(v, __shfl_xor_sync(0xffffffffu, v, o));
    return v;
}
__device__ __forceinline__ void mma_tf32(float c[4], const uint32_t a[4], const uint32_t b[2]) {
    asm volatile(
        "mma.sync.aligned.m16n8k8.row.col.f32.tf32.tf32.f32 "
        "{%0,%1,%2,%3}, {%4,%5,%6,%7}, {%8,%9}, {%0,%1,%2,%3};"
        : "+f"(c[0]), "+f"(c[1]), "+f"(c[2]), "+f"(c[3])
        : "r"(a[0]), "r"(a[1]), "r"(a[2]), "r"(a[3]), "r"(b[0]), "r"(b[1]));
}
#define CP_ASYNC16(dst_u32, src_ptr) \
    asm volatile("cp.async.cg.shared.global [%0], [%1], 16;" :: "r"(dst_u32), "l"(src_ptr))
#define CP_COMMIT() asm volatile("cp.async.commit_group;")
#define CP_WAIT(n)  asm volatile("cp.async.wait_group %0;" :: "n"(n))

// ---------------- LN(s)*w+b, width 512 ----------------
__global__ void __launch_bounds__(128) ln_affine512(
    const float* __restrict__ x, const float* __restrict__ w,
    const float* __restrict__ b, float* __restrict__ out)
{
    int row = blockIdx.x;
    const float4* xr = (const float4*)(x + (size_t)row * CND);
    float4 v = xr[threadIdx.x];
    float s  = v.x + v.y + v.z + v.w;
    float ss = v.x*v.x + v.y*v.y + v.z*v.z + v.w*v.w;
    s = warp_sum(s); ss = warp_sum(ss);
    __shared__ float sh[8];
    int wid = threadIdx.x >> 5, lid = threadIdx.x & 31;
    if (lid == 0) { sh[wid] = s; sh[4 + wid] = ss; }
    __syncthreads();
    s  = sh[0] + sh[1] + sh[2] + sh[3];
    ss = sh[4] + sh[5] + sh[6] + sh[7];
    float mean = s * (1.0f / CND);
    float var  = ss * (1.0f / CND) - mean * mean;
    float rinv = rsqrtf(var + EPSF);
    int d = threadIdx.x * 4;
    float4 wv = *(const float4*)(w + d);
    float4 bv = *(const float4*)(b + d);
    float4 o;
    o.x = (v.x - mean) * rinv * wv.x + bv.x;
    o.y = (v.y - mean) * rinv * wv.y + bv.y;
    o.z = (v.z - mean) * rinv * wv.z + bv.z;
    o.w = (v.w - mean) * rinv * wv.w + bv.w;
    ((float4*)(out + (size_t)row * CND))[threadIdx.x] = o;
}

// ---------------- LN(h)*(1+scale)+shift, width 1024 ----------------
__global__ void __launch_bounds__(256) ln_mod1024(
    const float* __restrict__ x, const float* __restrict__ mod,
    int scale_off, int shift_off, float* __restrict__ out)
{
    int row = blockIdx.x;
    float4 v = ((const float4*)(x + (size_t)row * CD))[threadIdx.x];
    float s  = v.x + v.y + v.z + v.w;
    float ss = v.x*v.x + v.y*v.y + v.z*v.z + v.w*v.w;
    s = warp_sum(s); ss = warp_sum(ss);
    __shared__ float sh[16];
    int wid = threadIdx.x >> 5, lid = threadIdx.x & 31;
    if (lid == 0) { sh[wid] = s; sh[8 + wid] = ss; }
    __syncthreads();
    s = 0.f; ss = 0.f;
#pragma unroll
    for (int i = 0; i < 8; i++) { s += sh[i]; ss += sh[8 + i]; }
    float mean = s * (1.0f / CD);
    float var  = ss * (1.0f / CD) - mean * mean;
    float rinv = rsqrtf(var + EPSF);
    int d = threadIdx.x * 4;
    const float* mrow = mod + (size_t)row * MODW;
    float4 sc = *(const float4*)(mrow + scale_off + d);
    float4 sf = *(const float4*)(mrow + shift_off + d);
    float4 o;
    o.x = ((v.x - mean) * rinv) * (1.0f + sc.x) + sf.x;
    o.y = ((v.y - mean) * rinv) * (1.0f + sc.y) + sf.y;
    o.z = ((v.z - mean) * rinv) * (1.0f + sc.z) + sf.z;
    o.w = ((v.w - mean) * rinv) * (1.0f + sc.w) + sf.w;
    ((float4*)(out + (size_t)row * CD))[threadIdx.x] = o;
}

// ---------------- tf32 NT GEMM, cp.async 2-stage pipeline ----------------
// Block 128x128x32, 256 threads, warp tile 64x32 (m16n8k8).
// Raw fp32 bits fed to tf32 MMA (HW truncation).
// EPI 0: +bias; EPI 1: silu(+bias); EPI 2: res + (+bias)*gate
#define GEMM_SMEM (2 * 2 * 128 * 36 * 4)
template<int EPI>
__global__ void __launch_bounds__(256) gemm_tf32(
    const float* __restrict__ A, const float* __restrict__ W,
    const float* __restrict__ bias, float* __restrict__ C,
    int M, int N, int K,
    const float* __restrict__ res, const float* __restrict__ gate, int gate_off)
{
    extern __shared__ float dynsm[];
    float (*As)[128][36] = (float(*)[128][36])dynsm;
    float (*Ws)[128][36] = (float(*)[128][36])(dynsm + 2 * 128 * 36);

    int bm = blockIdx.y * 128;
    int bn = blockIdx.x * 128;
    int tid  = threadIdx.x;
    int warp = tid >> 5, lane = tid & 31;
    int g = lane >> 2, t = lane & 3;
    int wm = (warp & 1) * 64;
    int wn = (warp >> 1) * 32;

    float acc[4][4][4];
#pragma unroll
    for (int i = 0; i < 4; i++)
#pragma unroll
        for (int j = 0; j < 4; j++)
#pragma unroll
            for (int q = 0; q < 4; q++) acc[i][j][q] = 0.f;

    int ldr = tid >> 3;              // 0..31 row group base
    int kv  = (tid & 7) * 4;         // 0..28

    // prologue: stage 0
#pragma unroll
    for (int r = 0; r < 4; r++) {
        int row = ldr + r * 32;
        uint32_t da = (uint32_t)__cvta_generic_to_shared(&As[0][row][kv]);
        CP_ASYNC16(da, A + (size_t)(bm + row) * K + kv);
        uint32_t dw = (uint32_t)__cvta_generic_to_shared(&Ws[0][row][kv]);
        CP_ASYNC16(dw, W + (size_t)(bn + row) * K + kv);
    }
    CP_COMMIT();

    int nIter = K >> 5;
    for (int it = 0; it < nIter; ++it) {
        if (it + 1 < nIter) {
            int k0n = (it + 1) << 5;
            int stn = (it + 1) & 1;
#pragma unroll
            for (int r = 0; r < 4; r++) {
                int row = ldr + r * 32;
                uint32_t da = (uint32_t)__cvta_generic_to_shared(&As[stn][row][kv]);
                CP_ASYNC16(da, A + (size_t)(bm + row) * K + k0n + kv);
                uint32_t dw = (uint32_t)__cvta_generic_to_shared(&Ws[stn][row][kv]);
                CP_ASYNC16(dw, W + (size_t)(bn + row) * K + k0n + kv);
            }
            CP_COMMIT();
            CP_WAIT(1);
        } else {
            CP_WAIT(0);
        }
        __syncthreads();
        int st = it & 1;
#pragma unroll
        for (int ks = 0; ks < 4; ks++) {
            int kk = ks * 8;
            uint32_t af[4][4];
#pragma unroll
            for (int mt = 0; mt < 4; mt++) {
                int r0 = wm + mt * 16 + g;
                af[mt][0] = __float_as_uint(As[st][r0][kk + t]);
                af[mt][1] = __float_as_uint(As[st][r0 + 8][kk + t]);
                af[mt][2] = __float_as_uint(As[st][r0][kk + t + 4]);
                af[mt][3] = __float_as_uint(As[st][r0 + 8][kk + t + 4]);
            }
            uint32_t bf[4][2];
#pragma unroll
            for (int nt = 0; nt < 4; nt++) {
                int c0 = wn + nt * 8 + g;
                bf[nt][0] = __float_as_uint(Ws[st][c0][kk + t]);
                bf[nt][1] = __float_as_uint(Ws[st][c0][kk + t + 4]);
            }
#pragma unroll
            for (int mt = 0; mt < 4; mt++)
#pragma unroll
                for (int nt = 0; nt < 4; nt++)
                    mma_tf32(acc[mt][nt], af[mt], bf[nt]);
        }
        __syncthreads();
    }

#pragma unroll
    for (int mt = 0; mt < 4; mt++) {
#pragma unroll
        for (int half = 0; half < 2; half++) {
            int row = bm + wm + mt * 16 + g + half * 8;
            float* cr = C + (size_t)row * N;
            const float* rr = (EPI == 2) ? res + (size_t)row * N : nullptr;
            const float* gr = (EPI == 2) ? gate + (size_t)row * MODW + gate_off : nullptr;
#pragma unroll
            for (int nt = 0; nt < 4; nt++) {
                int col = bn + wn + nt * 8 + 2 * t;
                float v0 = acc[mt][nt][half * 2 + 0] + bias[col];
                float v1 = acc[mt][nt][half * 2 + 1] + bias[col + 1];
                if (EPI == 1) {
                    v0 = v0 / (1.0f + expf(-v0));
                    v1 = v1 / (1.0f + expf(-v1));
                }
                if (EPI == 2) {
                    v0 = rr[col]     + v0 * gr[col];
                    v1 = rr[col + 1] + v1 * gr[col + 1];
                }
                float2 o2; o2.x = v0; o2.y = v1;
                *(float2*)(cr + col) = o2;
            }
        }
    }
}

// ---------------- edge bias v2: coalesced smem staging ----------------
// Block: 128 threads handle 128 rows of p (64 floats each).
__global__ void __launch_bounds__(128) edge_bias_k(
    const float* __restrict__ p, const float* __restrict__ lnw, const float* __restrict__ lnb,
    const float* __restrict__ ew, const float* __restrict__ eb, float* __restrict__ bias)
{
    __shared__ float rows[128][68];   // pad 68: 16B-aligned rows, conflict-free phases
    __shared__ float ewT[64][16];
    __shared__ float lnws[64], lnbs[64], ebs[16];
    int tid = threadIdx.x;
    for (int i = tid; i < 1024; i += 128) {
        int h = i >> 6, k = i & 63;
        ewT[k][h] = ew[i];
    }
    if (tid < 64) { lnws[tid] = lnw[tid]; lnbs[tid] = lnb[tid]; }
    if (tid < 16) ebs[tid] = eb[tid];

    size_t base = (size_t)blockIdx.x * 128;
    // coalesced load: 16 threads per row
#pragma unroll
    for (int r = 0; r < 16; r++) {
        int id  = tid + r * 128;
        int row = id >> 4;
        int c4  = (id & 15) * 4;
        *(float4*)&rows[row][c4] = *(const float4*)(p + (base + row) * 64 + c4);
    }
    __syncthreads();

    // per-thread row from smem (bank = (4*tid + k) % 32, conflict-free per 8-lane phase)
    float s = 0.f, ss = 0.f;
#pragma unroll
    for (int q = 0; q < 16; q++) {
        float4 x = *(const float4*)&rows[tid][q * 4];
        s  += x.x + x.y + x.z + x.w;
        ss += x.x*x.x + x.y*x.y + x.z*x.z + x.w*x.w;
    }
    float mean = s * (1.0f / 64.0f);
    float var  = ss * (1.0f / 64.0f) - mean * mean;
    float rinv = rsqrtf(var + EPSF);

    float acc[16];
#pragma unroll
    for (int h = 0; h < 16; h++) acc[h] = 0.f;

#pragma unroll
    for (int q = 0; q < 16; q++) {
        float4 x  = *(const float4*)&rows[tid][q * 4];
        float4 lw = *(const float4*)(lnws + q * 4);
        float4 lb = *(const float4*)(lnbs + q * 4);
        float pv[4] = { x.x, x.y, x.z, x.w };
        float wv[4] = { lw.x, lw.y, lw.z, lw.w };
        float bv[4] = { lb.x, lb.y, lb.z, lb.w };
#pragma unroll
        for (int u = 0; u < 4; u++) {
            int k = q * 4 + u;
            float pb = (pv[u] - mean) * rinv * wv[u] + bv[u];
            const float4* e4 = (const float4*)ewT[k];
#pragma unroll
            for (int gi = 0; gi < 4; gi++) {
                float4 e = e4[gi];
                acc[gi*4+0] = fmaf(pb, e.x, acc[gi*4+0]);
                acc[gi*4+1] = fmaf(pb, e.y, acc[gi*4+1]);
                acc[gi*4+2] = fmaf(pb, e.z, acc[gi*4+2]);
                acc[gi*4+3] = fmaf(pb, e.w, acc[gi*4+3]);
            }
        }
    }

    size_t idx = base + tid;
    int b  = (int)(idx >> 18);
    int ij = (int)(idx & 262143);
    int i  = ij >> 9, j = ij & 511;
    float* bb = bias + (((size_t)b * 16) * 512 + i) * 512 + j;
#pragma unroll
    for (int h = 0; h < 16; h++)
        bb[(size_t)h * 512 * 512] = acc[h] + ebs[h];
}

// ---------------- scores via tf32 MMA: sc = Q@K^T/8 + sc (in-place bias) ----------------
__global__ void __launch_bounds__(256) score_mma(
    const float* __restrict__ qkv, float* __restrict__ sc)
{
    __shared__ float Qs[128][36];
    __shared__ float Ks[128][36];
    int bh = blockIdx.z; int b = bh >> 4, h = bh & 15;
    int i0 = blockIdx.y * 128, j0 = blockIdx.x * 128;
    int tid  = threadIdx.x;
    int warp = tid >> 5, lane = tid & 31;
    int g = lane >> 2, t = lane & 3;
    int wm = (warp & 1) * 64;
    int wn = (warp >> 1) * 32;
    const float* qb = qkv + (size_t)(b * CL) * (3 * CD) + h * CDH;
    const float* kb = qb + CD;

    float acc[4][4][4];
#pragma unroll
    for (int i = 0; i < 4; i++)
#pragma unroll
        for (int j = 0; j < 4; j++)
#pragma unroll
            for (int q = 0; q < 4; q++) acc[i][j][q] = 0.f;

#pragma unroll
    for (int k0 = 0; k0 < CDH; k0 += 32) {
#pragma unroll
        for (int r = 0; r < 4; r++) {
            int id  = tid + r * 256;
            int row = id >> 3;
            int kv  = (id & 7) * 4;
            *(float4*)&Qs[row][kv] = *(const float4*)(qb + (size_t)(i0 + row) * (3 * CD) + k0 + kv);
            *(float4*)&Ks[row][kv] = *(const float4*)(kb + (size_t)(j0 + row) * (3 * CD) + k0 + kv);
        }
        __syncthreads();
#pragma unroll
        for (int ks = 0; ks < 4; ks++) {
            int kk = ks * 8;
            uint32_t af[4][4];
#pragma unroll
            for (int mt = 0; mt < 4; mt++) {
                int r0 = wm + mt * 16 + g;
                af[mt][0] = __float_as_uint(Qs[r0][kk + t]);
                af[mt][1] = __float_as_uint(Qs[r0 + 8][kk + t]);
                af[mt][2] = __float_as_uint(Qs[r0][kk + t + 4]);
                af[mt][3] = __float_as_uint(Qs[r0 + 8][kk + t + 4]);
            }
            uint32_t bf[4][2];
#pragma unroll
            for (int nt = 0; nt < 4; nt++) {
                int c0 = wn + nt * 8 + g;
                bf[nt][0] = __float_as_uint(Ks[c0][kk + t]);
                bf[nt][1] = __float_as_uint(Ks[c0][kk + t + 4]);
            }
#pragma unroll
            for (int mt = 0; mt < 4; mt++)
#pragma unroll
                for (int nt = 0; nt < 4; nt++)
                    mma_tf32(acc[mt][nt], af[mt], bf[nt]);
        }
        __syncthreads();
    }

    const float inv8 = 0.125f;
    float* scb = sc + (size_t)bh * CL * CL;
#pragma unroll
    for (int mt = 0; mt < 4; mt++) {
#pragma unroll
        for (int half = 0; half < 2; half++) {
            int row = i0 + wm + mt * 16 + g + half * 8;
            float* cr = scb + (size_t)row * CL;
#pragma unroll
            for (int nt = 0; nt < 4; nt++) {
                int col = j0 + wn + nt * 8 + 2 * t;
                float2 e = *(float2*)(cr + col);
                e.x = fmaf(acc[mt][nt][half * 2 + 0], inv8, e.x);
                e.y = fmaf(acc[mt][nt][half * 2 + 1], inv8, e.y);
                *(float2*)(cr + col) = e;
            }
        }
    }
}

// ---------------- softmax over rows of 512, in-place ----------------
__global__ void __launch_bounds__(128) softmax512(float* __restrict__ s)
{
    size_t row = blockIdx.x;
    float4* r = (float4*)(s + row * 512);
    float4 v = r[threadIdx.x];
    float m = fmaxf(fmaxf(v.x, v.y), fmaxf(v.z, v.w));
    m = warp_max(m);
    __shared__ float sh[8];
    int wid = threadIdx.x >> 5, lid = threadIdx.x & 31;
    if (lid == 0) sh[wid] = m;
    __syncthreads();
    m = fmaxf(fmaxf(sh[0], sh[1]), fmaxf(sh[2], sh[3]));
    v.x = expf(v.x - m); v.y = expf(v.y - m);
    v.z = expf(v.z - m); v.w = expf(v.w - m);
    float su = v.x + v.y + v.z + v.w;
    su = warp_sum(su);
    if (lid == 0) sh[4 + wid] = su;
    __syncthreads();
    su = sh[4] + sh[5] + sh[6] + sh[7];
    float inv = 1.0f / su;
    v.x *= inv; v.y *= inv; v.z *= inv; v.w *= inv;
    r[threadIdx.x] = v;
}

// ---------------- attn @ V via tf32 MMA (NN GEMM, V staged [k][n]) ----------------
__global__ void __launch_bounds__(256) attnv_mma(
    const float* __restrict__ attn, const float* __restrict__ qkv, float* __restrict__ o)
{
    __shared__ float Ps[128][36];
    __shared__ float Vs[32][68];
    int bh = blockIdx.y; int b = bh >> 4, h = bh & 15;
    int i0 = blockIdx.x * 128;
    int tid  = threadIdx.x;
    int warp = tid >> 5, lane = tid & 31;
    int g = lane >> 2, t = lane & 3;
    int wm = (warp & 3) * 32;        // 4 warps in M
    int wn = (warp >> 2) * 32;       // 2 warps in N
    const float* abase = attn + ((size_t)bh * CL + i0) * CL;
    const float* vbase = qkv + (size_t)(b * CL) * (3 * CD) + 2 * CD + h * CDH;

    float acc[2][4][4];
#pragma unroll
    for (int i = 0; i < 2; i++)
#pragma unroll
        for (int j = 0; j < 4; j++)
#pragma unroll
            for (int q = 0; q < 4; q++) acc[i][j][q] = 0.f;

    for (int j0 = 0; j0 < CL; j0 += 32) {
#pragma unroll
        for (int r = 0; r < 4; r++) {
            int id  = tid + r * 256;
            int row = id >> 3;
            int jv  = (id & 7) * 4;
            *(float4*)&Ps[row][jv] = *(const float4*)(abase + (size_t)row * CL + j0 + jv);
        }
#pragma unroll
        for (int r = 0; r < 2; r++) {
            int id = tid + r * 256;
            int kk = id >> 4;
            int dv = (id & 15) * 4;
            *(float4*)&Vs[kk][dv] = *(const float4*)(vbase + (size_t)(j0 + kk) * (3 * CD) + dv);
        }
        __syncthreads();
#pragma unroll
        for (int ks = 0; ks < 4; ks++) {
            int kk = ks * 8;
            uint32_t af[2][4];
#pragma unroll
            for (int mt = 0; mt < 2; mt++) {
                int r0 = wm + mt * 16 + g;
                af[mt][0] = __float_as_uint(Ps[r0][kk + t]);
                af[mt][1] = __float_as_uint(Ps[r0 + 8][kk + t]);
                af[mt][2] = __float_as_uint(Ps[r0][kk + t + 4]);
                af[mt][3] = __float_as_uint(Ps[r0 + 8][kk + t + 4]);
            }
            uint32_t bf[4][2];
#pragma unroll
            for (int nt = 0; nt < 4; nt++) {
                int c0 = wn + nt * 8 + g;
                bf[nt][0] = __float_as_uint(Vs[kk + t][c0]);
                bf[nt][1] = __float_as_uint(Vs[kk + t + 4][c0]);
            }
#pragma unroll
            for (int mt = 0; mt < 2; mt++)
#pragma unroll
                for (int nt = 0; nt < 4; nt++)
                    mma_tf32(acc[mt][nt], af[mt], bf[nt]);
        }
        __syncthreads();
    }

#pragma unroll
    for (int mt = 0; mt < 2; mt++) {
#pragma unroll
        for (int half = 0; half < 2; half++) {
            int i = i0 + wm + mt * 16 + g + half * 8;
            float* orow = o + (size_t)(b * CL + i) * CD + h * CDH;
#pragma unroll
            for (int nt = 0; nt < 4; nt++) {
                int d = wn + nt * 8 + 2 * t;
                float2 w;
                w.x = acc[mt][nt][half * 2 + 0];
                w.y = acc[mt][nt][half * 2 + 1];
                *(float2*)(orow + d) = w;
            }
        }
    }
}

// ---------------- launch ----------------
extern "C" void kernel_launch(void* const* d_in, const int* in_sizes, int n_in,
                              void* d_out, int out_size)
{
    const float* h_in  = (const float*)d_in[0];
    const float* s_in  = (const float*)d_in[1];
    const float* p_in  = (const float*)d_in[2];
    const float* aln_w = (const float*)d_in[3];
    const float* aln_b = (const float*)d_in[4];
    const float* aw1   = (const float*)d_in[5];
    const float* ab1   = (const float*)d_in[6];
    const float* aw2   = (const float*)d_in[7];
    const float* ab2   = (const float*)d_in[8];
    const float* eln_w = (const float*)d_in[9];
    const float* eln_b = (const float*)d_in[10];
    const float* ew    = (const float*)d_in[11];
    const float* eb    = (const float*)d_in[12];
    const float* in_w  = (const float*)d_in[13];
    const float* in_b  = (const float*)d_in[14];
    const float* out_w = (const float*)d_in[15];
    const float* out_b = (const float*)d_in[16];
    const float* mw1   = (const float*)d_in[17];
    const float* mb1   = (const float*)d_in[18];
    const float* mw2   = (const float*)d_in[19];
    const float* mb2   = (const float*)d_in[20];
    float* out = (float*)d_out;

    float *sln, *t1, *mod, *scores, *x, *qkv, *o, *h2, *t2;
    cudaGetSymbolAddress((void**)&sln,    g_sln);
    cudaGetSymbolAddress((void**)&t1,     g_t1);
    cudaGetSymbolAddress((void**)&mod,    g_mod);
    cudaGetSymbolAddress((void**)&scores, g_scores);
    cudaGetSymbolAddress((void**)&x,      g_x);
    cudaGetSymbolAddress((void**)&qkv,    g_qkv);
    cudaGetSymbolAddress((void**)&o,      g_o);
    cudaGetSymbolAddress((void**)&h2,     g_h2);
    cudaGetSymbolAddress((void**)&t2,     g_t2);

    cudaFuncSetAttribute(gemm_tf32<0>, cudaFuncAttributeMaxDynamicSharedMemorySize, GEMM_SMEM);
    cudaFuncSetAttribute(gemm_tf32<1>, cudaFuncAttributeMaxDynamicSharedMemorySize, GEMM_SMEM);
    cudaFuncSetAttribute(gemm_tf32<2>, cudaFuncAttributeMaxDynamicSharedMemorySize, GEMM_SMEM);

    // adaLN modulation chain
    ln_affine512<<<NTOK, 128>>>(s_in, aln_w, aln_b, sln);
    gemm_tf32<1><<<dim3(CND / 128, NTOK / 128), 256, GEMM_SMEM>>>(sln, aw1, ab1, t1,
        NTOK, CND, CND, nullptr, nullptr, 0);
    gemm_tf32<0><<<dim3(MODW / 128, NTOK / 128), 256, GEMM_SMEM>>>(t1, aw2, ab2, mod,
        NTOK, MODW, CND, nullptr, nullptr, 0);

    // edge bias (writes into scores buffer)
    edge_bias_k<<<(CB * CL * CL) / 128, 128>>>(p_in, eln_w, eln_b, ew, eb, scores);

    // attention branch
    ln_mod1024<<<NTOK, 256>>>(h_in, mod, /*scale*/CD, /*shift*/0, x);
    gemm_tf32<0><<<dim3(3 * CD / 128, NTOK / 128), 256, GEMM_SMEM>>>(x, in_w, in_b, qkv,
        NTOK, 3 * CD, CD, nullptr, nullptr, 0);
    score_mma<<<dim3(4, 4, CB * CH), 256>>>(qkv, scores);
    softmax512<<<CB * CH * CL, 128>>>(scores);
    attnv_mma<<<dim3(4, CB * CH), 256>>>(scores, qkv, o);
    gemm_tf32<2><<<dim3(CD / 128, NTOK / 128), 256, GEMM_SMEM>>>(o, out_w, out_b, h2,
        NTOK, CD, CD, h_in, mod, 2 * CD);

    // gated MLP branch
    ln_mod1024<<<NTOK, 256>>>(h2, mod, /*scale*/4 * CD, /*shift*/3 * CD, x);
    gemm_tf32<1><<<dim3(CMLP / 128, NTOK / 128), 256, GEMM_SMEM>>>(x, mw1, mb1, t2,
        NTOK, CMLP, CD, nullptr, nullptr, 0);
    gemm_tf32<2><<<dim3(CD / 128, NTOK / 128), 256, GEMM_SMEM>>>(t2, mw2, mb2, out,
        NTOK, CD, CMLP, h2, mod, 5 * CD);
}

// round 4
// speedup vs baseline: 2.7761x; 1.0912x over previous
#include <cuda_runtime.h>
#include <math.h>
#include <stdint.h>

// Problem constants
#define CB   4
#define CL   512
#define CD   1024
#define CND  512
#define CED  64
#define CH   16
#define CMLP 2048
#define CDH  64
#define NTOK (CB*CL)        // 2048
#define MODW (6*CD)         // 6144
#define EPSF 1e-5f

// ---------------- scratch ----------------
__device__ float g_sln[NTOK*CND];
__device__ float g_t1[NTOK*CND];
__device__ float g_mod[NTOK*MODW];
__device__ float g_scores[(size_t)CB*CH*CL*CL];
__device__ float g_x[NTOK*CD];
__device__ float g_qkv[NTOK*3*CD];
__device__ float g_o[NTOK*CD];
__device__ float g_h2[NTOK*CD];
__device__ float g_t2[NTOK*CMLP];

// ---------------- utils ----------------
__device__ __forceinline__ float warp_sum(float v) {
#pragma unroll
    for (int o = 16; o > 0; o >>= 1) v += __shfl_xor_sync(0xffffffffu, v, o);
    return v;
}
__device__ __forceinline__ float warp_max(float v) {
#pragma unroll
    for (int o = 16; o > 0; o >>= 1) v = fmaxf(v, __shfl_xor_sync(0xffffffffu, v, o));
    return v;
}
__device__ __forceinline__ void mma_tf32(float c[4], const uint32_t a[4], const uint32_t b[2]) {
    asm volatile(
        "mma.sync.aligned.m16n8k8.row.col.f32.tf32.tf32.f32 "
        "{%0,%1,%2,%3}, {%4,%5,%6,%7}, {%8,%9}, {%0,%1,%2,%3};"
        : "+f"(c[0]), "+f"(c[1]), "+f"(c[2]), "+f"(c[3])
        : "r"(a[0]), "r"(a[1]), "r"(a[2]), "r"(a[3]), "r"(b[0]), "r"(b[1]));
}
#define CP_ASYNC16(dst_u32, src_ptr) \
    asm volatile("cp.async.cg.shared.global [%0], [%1], 16;" :: "r"(dst_u32), "l"(src_ptr))
#define CP_COMMIT() asm volatile("cp.async.commit_group;")
#define CP_WAIT(n)  asm volatile("cp.async.wait_group %0;" :: "n"(n))

// ---------------- LN(s)*w+b, width 512 ----------------
__global__ void __launch_bounds__(128) ln_affine512(
    const float* __restrict__ x, const float* __restrict__ w,
    const float* __restrict__ b, float* __restrict__ out)
{
    int row = blockIdx.x;
    const float4* xr = (const float4*)(x + (size_t)row * CND);
    float4 v = xr[threadIdx.x];
    float s  = v.x + v.y + v.z + v.w;
    float ss = v.x*v.x + v.y*v.y + v.z*v.z + v.w*v.w;
    s = warp_sum(s); ss = warp_sum(ss);
    __shared__ float sh[8];
    int wid = threadIdx.x >> 5, lid = threadIdx.x & 31;
    if (lid == 0) { sh[wid] = s; sh[4 + wid] = ss; }
    __syncthreads();
    s  = sh[0] + sh[1] + sh[2] + sh[3];
    ss = sh[4] + sh[5] + sh[6] + sh[7];
    float mean = s * (1.0f / CND);
    float var  = ss * (1.0f / CND) - mean * mean;
    float rinv = rsqrtf(var + EPSF);
    int d = threadIdx.x * 4;
    float4 wv = *(const float4*)(w + d);
    float4 bv = *(const float4*)(b + d);
    float4 o;
    o.x = (v.x - mean) * rinv * wv.x + bv.x;
    o.y = (v.y - mean) * rinv * wv.y + bv.y;
    o.z = (v.z - mean) * rinv * wv.z + bv.z;
    o.w = (v.w - mean) * rinv * wv.w + bv.w;
    ((float4*)(out + (size_t)row * CND))[threadIdx.x] = o;
}

// ---------------- LN(h)*(1+scale)+shift, width 1024 ----------------
__global__ void __launch_bounds__(256) ln_mod1024(
    const float* __restrict__ x, const float* __restrict__ mod,
    int scale_off, int shift_off, float* __restrict__ out)
{
    int row = blockIdx.x;
    float4 v = ((const float4*)(x + (size_t)row * CD))[threadIdx.x];
    float s  = v.x + v.y + v.z + v.w;
    float ss = v.x*v.x + v.y*v.y + v.z*v.z + v.w*v.w;
    s = warp_sum(s); ss = warp_sum(ss);
    __shared__ float sh[16];
    int wid = threadIdx.x >> 5, lid = threadIdx.x & 31;
    if (lid == 0) { sh[wid] = s; sh[8 + wid] = ss; }
    __syncthreads();
    s = 0.f; ss = 0.f;
#pragma unroll
    for (int i = 0; i < 8; i++) { s += sh[i]; ss += sh[8 + i]; }
    float mean = s * (1.0f / CD);
    float var  = ss * (1.0f / CD) - mean * mean;
    float rinv = rsqrtf(var + EPSF);
    int d = threadIdx.x * 4;
    const float* mrow = mod + (size_t)row * MODW;
    float4 sc = *(const float4*)(mrow + scale_off + d);
    float4 sf = *(const float4*)(mrow + shift_off + d);
    float4 o;
    o.x = ((v.x - mean) * rinv) * (1.0f + sc.x) + sf.x;
    o.y = ((v.y - mean) * rinv) * (1.0f + sc.y) + sf.y;
    o.z = ((v.z - mean) * rinv) * (1.0f + sc.z) + sf.z;
    o.w = ((v.w - mean) * rinv) * (1.0f + sc.w) + sf.w;
    ((float4*)(out + (size_t)row * CD))[threadIdx.x] = o;
}

// ---------------- tf32 NT GEMM, cp.async 2-stage, 2 CTAs/SM ----------------
#define GEMM_SMEM (2 * 2 * 128 * 36 * 4)
template<int EPI>
__global__ void __launch_bounds__(256, 2) gemm_tf32(
    const float* __restrict__ A, const float* __restrict__ W,
    const float* __restrict__ bias, float* __restrict__ C,
    int M, int N, int K,
    const float* __restrict__ res, const float* __restrict__ gate, int gate_off)
{
    extern __shared__ float dynsm[];
    float (*As)[128][36] = (float(*)[128][36])dynsm;
    float (*Ws)[128][36] = (float(*)[128][36])(dynsm + 2 * 128 * 36);

    int bm = blockIdx.y * 128;
    int bn = blockIdx.x * 128;
    int tid  = threadIdx.x;
    int warp = tid >> 5, lane = tid & 31;
    int g = lane >> 2, t = lane & 3;
    int wm = (warp & 1) * 64;
    int wn = (warp >> 1) * 32;

    float acc[4][4][4];
#pragma unroll
    for (int i = 0; i < 4; i++)
#pragma unroll
        for (int j = 0; j < 4; j++)
#pragma unroll
            for (int q = 0; q < 4; q++) acc[i][j][q] = 0.f;

    int ldr = tid >> 3;
    int kv  = (tid & 7) * 4;

#pragma unroll
    for (int r = 0; r < 4; r++) {
        int row = ldr + r * 32;
        uint32_t da = (uint32_t)__cvta_generic_to_shared(&As[0][row][kv]);
        CP_ASYNC16(da, A + (size_t)(bm + row) * K + kv);
        uint32_t dw = (uint32_t)__cvta_generic_to_shared(&Ws[0][row][kv]);
        CP_ASYNC16(dw, W + (size_t)(bn + row) * K + kv);
    }
    CP_COMMIT();

    int nIter = K >> 5;
    for (int it = 0; it < nIter; ++it) {
        if (it + 1 < nIter) {
            int k0n = (it + 1) << 5;
            int stn = (it + 1) & 1;
#pragma unroll
            for (int r = 0; r < 4; r++) {
                int row = ldr + r * 32;
                uint32_t da = (uint32_t)__cvta_generic_to_shared(&As[stn][row][kv]);
                CP_ASYNC16(da, A + (size_t)(bm + row) * K + k0n + kv);
                uint32_t dw = (uint32_t)__cvta_generic_to_shared(&Ws[stn][row][kv]);
                CP_ASYNC16(dw, W + (size_t)(bn + row) * K + k0n + kv);
            }
            CP_COMMIT();
            CP_WAIT(1);
        } else {
            CP_WAIT(0);
        }
        __syncthreads();
        int st = it & 1;
#pragma unroll
        for (int ks = 0; ks < 4; ks++) {
            int kk = ks * 8;
            uint32_t af[4][4];
#pragma unroll
            for (int mt = 0; mt < 4; mt++) {
                int r0 = wm + mt * 16 + g;
                af[mt][0] = __float_as_uint(As[st][r0][kk + t]);
                af[mt][1] = __float_as_uint(As[st][r0 + 8][kk + t]);
                af[mt][2] = __float_as_uint(As[st][r0][kk + t + 4]);
                af[mt][3] = __float_as_uint(As[st][r0 + 8][kk + t + 4]);
            }
            uint32_t bf[4][2];
#pragma unroll
            for (int nt = 0; nt < 4; nt++) {
                int c0 = wn + nt * 8 + g;
                bf[nt][0] = __float_as_uint(Ws[st][c0][kk + t]);
                bf[nt][1] = __float_as_uint(Ws[st][c0][kk + t + 4]);
            }
#pragma unroll
            for (int mt = 0; mt < 4; mt++)
#pragma unroll
                for (int nt = 0; nt < 4; nt++)
                    mma_tf32(acc[mt][nt], af[mt], bf[nt]);
        }
        __syncthreads();
    }

#pragma unroll
    for (int mt = 0; mt < 4; mt++) {
#pragma unroll
        for (int half = 0; half < 2; half++) {
            int row = bm + wm + mt * 16 + g + half * 8;
            float* cr = C + (size_t)row * N;
            const float* rr = (EPI == 2) ? res + (size_t)row * N : nullptr;
            const float* gr = (EPI == 2) ? gate + (size_t)row * MODW + gate_off : nullptr;
#pragma unroll
            for (int nt = 0; nt < 4; nt++) {
                int col = bn + wn + nt * 8 + 2 * t;
                float v0 = acc[mt][nt][half * 2 + 0] + bias[col];
                float v1 = acc[mt][nt][half * 2 + 1] + bias[col + 1];
                if (EPI == 1) {
                    v0 = v0 / (1.0f + expf(-v0));
                    v1 = v1 / (1.0f + expf(-v1));
                }
                if (EPI == 2) {
                    v0 = rr[col]     + v0 * gr[col];
                    v1 = rr[col + 1] + v1 * gr[col + 1];
                }
                float2 o2; o2.x = v0; o2.y = v1;
                *(float2*)(cr + col) = o2;
            }
        }
    }
}

// ---------------- edge bias: coalesced smem staging ----------------
__global__ void __launch_bounds__(128) edge_bias_k(
    const float* __restrict__ p, const float* __restrict__ lnw, const float* __restrict__ lnb,
    const float* __restrict__ ew, const float* __restrict__ eb, float* __restrict__ bias)
{
    __shared__ float rows[128][68];
    __shared__ float ewT[64][16];
    __shared__ float lnws[64], lnbs[64], ebs[16];
    int tid = threadIdx.x;
    for (int i = tid; i < 1024; i += 128) {
        int h = i >> 6, k = i & 63;
        ewT[k][h] = ew[i];
    }
    if (tid < 64) { lnws[tid] = lnw[tid]; lnbs[tid] = lnb[tid]; }
    if (tid < 16) ebs[tid] = eb[tid];

    size_t base = (size_t)blockIdx.x * 128;
#pragma unroll
    for (int r = 0; r < 16; r++) {
        int id  = tid + r * 128;
        int row = id >> 4;
        int c4  = (id & 15) * 4;
        *(float4*)&rows[row][c4] = *(const float4*)(p + (base + row) * 64 + c4);
    }
    __syncthreads();

    float s = 0.f, ss = 0.f;
#pragma unroll
    for (int q = 0; q < 16; q++) {
        float4 x = *(const float4*)&rows[tid][q * 4];
        s  += x.x + x.y + x.z + x.w;
        ss += x.x*x.x + x.y*x.y + x.z*x.z + x.w*x.w;
    }
    float mean = s * (1.0f / 64.0f);
    float var  = ss * (1.0f / 64.0f) - mean * mean;
    float rinv = rsqrtf(var + EPSF);

    float acc[16];
#pragma unroll
    for (int h = 0; h < 16; h++) acc[h] = 0.f;

#pragma unroll
    for (int q = 0; q < 16; q++) {
        float4 x  = *(const float4*)&rows[tid][q * 4];
        float4 lw = *(const float4*)(lnws + q * 4);
        float4 lb = *(const float4*)(lnbs + q * 4);
        float pv[4] = { x.x, x.y, x.z, x.w };
        float wv[4] = { lw.x, lw.y, lw.z, lw.w };
        float bv[4] = { lb.x, lb.y, lb.z, lb.w };
#pragma unroll
        for (int u = 0; u < 4; u++) {
            int k = q * 4 + u;
            float pb = (pv[u] - mean) * rinv * wv[u] + bv[u];
            const float4* e4 = (const float4*)ewT[k];
#pragma unroll
            for (int gi = 0; gi < 4; gi++) {
                float4 e = e4[gi];
                acc[gi*4+0] = fmaf(pb, e.x, acc[gi*4+0]);
                acc[gi*4+1] = fmaf(pb, e.y, acc[gi*4+1]);
                acc[gi*4+2] = fmaf(pb, e.z, acc[gi*4+2]);
                acc[gi*4+3] = fmaf(pb, e.w, acc[gi*4+3]);
            }
        }
    }

    size_t idx = base + tid;
    int b  = (int)(idx >> 18);
    int ij = (int)(idx & 262143);
    int i  = ij >> 9, j = ij & 511;
    float* bb = bias + (((size_t)b * 16) * 512 + i) * 512 + j;
#pragma unroll
    for (int h = 0; h < 16; h++)
        bb[(size_t)h * 512 * 512] = acc[h] + ebs[h];
}

// ---------------- scores via tf32 MMA: sc = Q@K^T/8 + sc ----------------
__global__ void __launch_bounds__(256) score_mma(
    const float* __restrict__ qkv, float* __restrict__ sc)
{
    __shared__ float Qs[128][36];
    __shared__ float Ks[128][36];
    int bh = blockIdx.z; int b = bh >> 4, h = bh & 15;
    int i0 = blockIdx.y * 128, j0 = blockIdx.x * 128;
    int tid  = threadIdx.x;
    int warp = tid >> 5, lane = tid & 31;
    int g = lane >> 2, t = lane & 3;
    int wm = (warp & 1) * 64;
    int wn = (warp >> 1) * 32;
    const float* qb = qkv + (size_t)(b * CL) * (3 * CD) + h * CDH;
    const float* kb = qb + CD;

    float acc[4][4][4];
#pragma unroll
    for (int i = 0; i < 4; i++)
#pragma unroll
        for (int j = 0; j < 4; j++)
#pragma unroll
            for (int q = 0; q < 4; q++) acc[i][j][q] = 0.f;

#pragma unroll
    for (int k0 = 0; k0 < CDH; k0 += 32) {
#pragma unroll
        for (int r = 0; r < 4; r++) {
            int id  = tid + r * 256;
            int row = id >> 3;
            int kv  = (id & 7) * 4;
            *(float4*)&Qs[row][kv] = *(const float4*)(qb + (size_t)(i0 + row) * (3 * CD) + k0 + kv);
            *(float4*)&Ks[row][kv] = *(const float4*)(kb + (size_t)(j0 + row) * (3 * CD) + k0 + kv);
        }
        __syncthreads();
#pragma unroll
        for (int ks = 0; ks < 4; ks++) {
            int kk = ks * 8;
            uint32_t af[4][4];
#pragma unroll
            for (int mt = 0; mt < 4; mt++) {
                int r0 = wm + mt * 16 + g;
                af[mt][0] = __float_as_uint(Qs[r0][kk + t]);
                af[mt][1] = __float_as_uint(Qs[r0 + 8][kk + t]);
                af[mt][2] = __float_as_uint(Qs[r0][kk + t + 4]);
                af[mt][3] = __float_as_uint(Qs[r0 + 8][kk + t + 4]);
            }
            uint32_t bf[4][2];
#pragma unroll
            for (int nt = 0; nt < 4; nt++) {
                int c0 = wn + nt * 8 + g;
                bf[nt][0] = __float_as_uint(Ks[c0][kk + t]);
                bf[nt][1] = __float_as_uint(Ks[c0][kk + t + 4]);
            }
#pragma unroll
            for (int mt = 0; mt < 4; mt++)
#pragma unroll
                for (int nt = 0; nt < 4; nt++)
                    mma_tf32(acc[mt][nt], af[mt], bf[nt]);
        }
        __syncthreads();
    }

    const float inv8 = 0.125f;
    float* scb = sc + (size_t)bh * CL * CL;
#pragma unroll
    for (int mt = 0; mt < 4; mt++) {
#pragma unroll
        for (int half = 0; half < 2; half++) {
            int row = i0 + wm + mt * 16 + g + half * 8;
            float* cr = scb + (size_t)row * CL;
#pragma unroll
            for (int nt = 0; nt < 4; nt++) {
                int col = j0 + wn + nt * 8 + 2 * t;
                float2 e = *(float2*)(cr + col);
                e.x = fmaf(acc[mt][nt][half * 2 + 0], inv8, e.x);
                e.y = fmaf(acc[mt][nt][half * 2 + 1], inv8, e.y);
                *(float2*)(cr + col) = e;
            }
        }
    }
}

// ---------------- fused softmax + attn@V ----------------
// Pass 1: per-row max, write exp(x-max) in place, keep 1/sum in smem.
// Pass 2: P@V via tf32 MMA (P read back, L2-hot), scale output by 1/sum.
__global__ void __launch_bounds__(256) attnv_mma(
    float* __restrict__ attn, const float* __restrict__ qkv, float* __restrict__ o)
{
    __shared__ float Ps[128][36];
    __shared__ float Vs[32][68];
    __shared__ float invs[128];
    int bh = blockIdx.y; int b = bh >> 4, h = bh & 15;
    int i0 = blockIdx.x * 128;
    int tid  = threadIdx.x;
    int warp = tid >> 5, lane = tid & 31;
    int g = lane >> 2, t = lane & 3;
    int wm = (warp & 3) * 32;
    int wn = (warp >> 2) * 32;
    float* abase = attn + ((size_t)bh * CL + i0) * CL;
    const float* vbase = qkv + (size_t)(b * CL) * (3 * CD) + 2 * CD + h * CDH;

    // pass 1: softmax (exp in place, invsum to smem)
#pragma unroll
    for (int rr = 0; rr < 16; rr++) {
        int row = warp * 16 + rr;
        float* rp = abase + (size_t)row * CL;
        float4 v[4];
        float m = -1e30f;
#pragma unroll
        for (int c = 0; c < 4; c++) {
            v[c] = *(float4*)(rp + c * 128 + lane * 4);
            m = fmaxf(m, fmaxf(fmaxf(v[c].x, v[c].y), fmaxf(v[c].z, v[c].w)));
        }
        m = warp_max(m);
        float su = 0.f;
#pragma unroll
        for (int c = 0; c < 4; c++) {
            v[c].x = expf(v[c].x - m); v[c].y = expf(v[c].y - m);
            v[c].z = expf(v[c].z - m); v[c].w = expf(v[c].w - m);
            su += v[c].x + v[c].y + v[c].z + v[c].w;
            *(float4*)(rp + c * 128 + lane * 4) = v[c];
        }
        su = warp_sum(su);
        if (lane == 0) invs[row] = 1.0f / su;
    }
    __syncthreads();

    float acc[2][4][4];
#pragma unroll
    for (int i = 0; i < 2; i++)
#pragma unroll
        for (int j = 0; j < 4; j++)
#pragma unroll
            for (int q = 0; q < 4; q++) acc[i][j][q] = 0.f;

    int wmm = (warp & 3) * 32;
    int wnn = (warp >> 2) * 32;
    for (int j0 = 0; j0 < CL; j0 += 32) {
#pragma unroll
        for (int r = 0; r < 4; r++) {
            int id  = tid + r * 256;
            int row = id >> 3;
            int jv  = (id & 7) * 4;
            *(float4*)&Ps[row][jv] = *(const float4*)(abase + (size_t)row * CL + j0 + jv);
        }
#pragma unroll
        for (int r = 0; r < 2; r++) {
            int id = tid + r * 256;
            int kk = id >> 4;
            int dv = (id & 15) * 4;
            *(float4*)&Vs[kk][dv] = *(const float4*)(vbase + (size_t)(j0 + kk) * (3 * CD) + dv);
        }
        __syncthreads();
#pragma unroll
        for (int ks = 0; ks < 4; ks++) {
            int kk = ks * 8;
            uint32_t af[2][4];
#pragma unroll
            for (int mt = 0; mt < 2; mt++) {
                int r0 = wmm + mt * 16 + g;
                af[mt][0] = __float_as_uint(Ps[r0][kk + t]);
                af[mt][1] = __float_as_uint(Ps[r0 + 8][kk + t]);
                af[mt][2] = __float_as_uint(Ps[r0][kk + t + 4]);
                af[mt][3] = __float_as_uint(Ps[r0 + 8][kk + t + 4]);
            }
            uint32_t bf[4][2];
#pragma unroll
            for (int nt = 0; nt < 4; nt++) {
                int c0 = wnn + nt * 8 + g;
                bf[nt][0] = __float_as_uint(Vs[kk + t][c0]);
                bf[nt][1] = __float_as_uint(Vs[kk + t + 4][c0]);
            }
#pragma unroll
            for (int mt = 0; mt < 2; mt++)
#pragma unroll
                for (int nt = 0; nt < 4; nt++)
                    mma_tf32(acc[mt][nt], af[mt], bf[nt]);
        }
        __syncthreads();
    }

#pragma unroll
    for (int mt = 0; mt < 2; mt++) {
#pragma unroll
        for (int half = 0; half < 2; half++) {
            int li = wmm + mt * 16 + g + half * 8;
            float sc = invs[li];
            int i = i0 + li;
            float* orow = o + (size_t)(b * CL + i) * CD + h * CDH;
#pragma unroll
            for (int nt = 0; nt < 4; nt++) {
                int d = wnn + nt * 8 + 2 * t;
                float2 w;
                w.x = acc[mt][nt][half * 2 + 0] * sc;
                w.y = acc[mt][nt][half * 2 + 1] * sc;
                *(float2*)(orow + d) = w;
            }
        }
    }
}

// ---------------- launch ----------------
extern "C" void kernel_launch(void* const* d_in, const int* in_sizes, int n_in,
                              void* d_out, int out_size)
{
    const float* h_in  = (const float*)d_in[0];
    const float* s_in  = (const float*)d_in[1];
    const float* p_in  = (const float*)d_in[2];
    const float* aln_w = (const float*)d_in[3];
    const float* aln_b = (const float*)d_in[4];
    const float* aw1   = (const float*)d_in[5];
    const float* ab1   = (const float*)d_in[6];
    const float* aw2   = (const float*)d_in[7];
    const float* ab2   = (const float*)d_in[8];
    const float* eln_w = (const float*)d_in[9];
    const float* eln_b = (const float*)d_in[10];
    const float* ew    = (const float*)d_in[11];
    const float* eb    = (const float*)d_in[12];
    const float* in_w  = (const float*)d_in[13];
    const float* in_b  = (const float*)d_in[14];
    const float* out_w = (const float*)d_in[15];
    const float* out_b = (const float*)d_in[16];
    const float* mw1   = (const float*)d_in[17];
    const float* mb1   = (const float*)d_in[18];
    const float* mw2   = (const float*)d_in[19];
    const float* mb2   = (const float*)d_in[20];
    float* out = (float*)d_out;

    float *sln, *t1, *mod, *scores, *x, *qkv, *o, *h2, *t2;
    cudaGetSymbolAddress((void**)&sln,    g_sln);
    cudaGetSymbolAddress((void**)&t1,     g_t1);
    cudaGetSymbolAddress((void**)&mod,    g_mod);
    cudaGetSymbolAddress((void**)&scores, g_scores);
    cudaGetSymbolAddress((void**)&x,      g_x);
    cudaGetSymbolAddress((void**)&qkv,    g_qkv);
    cudaGetSymbolAddress((void**)&o,      g_o);
    cudaGetSymbolAddress((void**)&h2,     g_h2);
    cudaGetSymbolAddress((void**)&t2,     g_t2);

    cudaFuncSetAttribute(gemm_tf32<0>, cudaFuncAttributeMaxDynamicSharedMemorySize, GEMM_SMEM);
    cudaFuncSetAttribute(gemm_tf32<1>, cudaFuncAttributeMaxDynamicSharedMemorySize, GEMM_SMEM);
    cudaFuncSetAttribute(gemm_tf32<2>, cudaFuncAttributeMaxDynamicSharedMemorySize, GEMM_SMEM);

    // adaLN modulation chain
    ln_affine512<<<NTOK, 128>>>(s_in, aln_w, aln_b, sln);
    gemm_tf32<1><<<dim3(CND / 128, NTOK / 128), 256, GEMM_SMEM>>>(sln, aw1, ab1, t1,
        NTOK, CND, CND, nullptr, nullptr, 0);
    gemm_tf32<0><<<dim3(MODW / 128, NTOK / 128), 256, GEMM_SMEM>>>(t1, aw2, ab2, mod,
        NTOK, MODW, CND, nullptr, nullptr, 0);

    // edge bias (writes into scores buffer)
    edge_bias_k<<<(CB * CL * CL) / 128, 128>>>(p_in, eln_w, eln_b, ew, eb, scores);

    // attention branch
    ln_mod1024<<<NTOK, 256>>>(h_in, mod, /*scale*/CD, /*shift*/0, x);
    gemm_tf32<0><<<dim3(3 * CD / 128, NTOK / 128), 256, GEMM_SMEM>>>(x, in_w, in_b, qkv,
        NTOK, 3 * CD, CD, nullptr, nullptr, 0);
    score_mma<<<dim3(4, 4, CB * CH), 256>>>(qkv, scores);
    attnv_mma<<<dim3(4, CB * CH), 256>>>(scores, qkv, o);
    gemm_tf32<2><<<dim3(CD / 128, NTOK / 128), 256, GEMM_SMEM>>>(o, out_w, out_b, h2,
        NTOK, CD, CD, h_in, mod, 2 * CD);

    // gated MLP branch
    ln_mod1024<<<NTOK, 256>>>(h2, mod, /*scale*/4 * CD, /*shift*/3 * CD, x);
    gemm_tf32<1><<<dim3(CMLP / 128, NTOK / 128), 256, GEMM_SMEM>>>(x, mw1, mb1, t2,
        NTOK, CMLP, CD, nullptr, nullptr, 0);
    gemm_tf32<2><<<dim3(CD / 128, NTOK / 128), 256, GEMM_SMEM>>>(t2, mw2, mb2, out,
        NTOK, CD, CMLP, h2, mod, 5 * CD);
}